// round 2
// baseline (speedup 1.0000x reference)
#include <cuda_runtime.h>

// Problem constants (from reference)
#define NMAX 50000
#define EMAX 800000
#define NODE_F 64
#define EDGE_F 16
#define HID 64
#define OUTF 32

// ---------------- scratch (device globals; no allocation allowed) ----------
__device__ int   g_cnt[NMAX];
__device__ int   g_rowptr[NMAX + 1];
__device__ int   g_cursor[NMAX];
__device__ int   g_csr_src[EMAX];
__device__ int   g_csr_eid[EMAX];
__device__ float g_agge[NMAX * EDGE_F];   // segment_sum(edge_attr) — reused by both layers
__device__ float g_aggx[NMAX * 64];       // A@x (layer1), then A@h (layer2)
__device__ float g_h[NMAX * HID];         // post BN+ReLU hidden

// ---------------- CSR build ------------------------------------------------
__global__ void k_zero(int N) {
    int i = blockIdx.x * blockDim.x + threadIdx.x;
    if (i < N) g_cnt[i] = 0;
}

__global__ void k_hist(const int* __restrict__ dst, int E) {
    int e = blockIdx.x * blockDim.x + threadIdx.x;
    if (e < E) atomicAdd(&g_cnt[dst[e]], 1);
}

// single-block scan over N elements (exclusive prefix -> rowptr, cursor)
__global__ void k_scan(int N) {
    __shared__ int sWarp[32];
    __shared__ int sCarry;
    int tid = threadIdx.x;
    int lane = tid & 31, wid = tid >> 5;
    if (tid == 0) sCarry = 0;
    __syncthreads();
    for (int base = 0; base < N; base += 1024) {
        int i = base + tid;
        int c = (i < N) ? g_cnt[i] : 0;
        int v = c;
        #pragma unroll
        for (int o = 1; o < 32; o <<= 1) {
            int t = __shfl_up_sync(0xffffffffu, v, o);
            if (lane >= o) v += t;
        }
        if (lane == 31) sWarp[wid] = v;
        __syncthreads();
        if (wid == 0) {
            int w = sWarp[lane];
            #pragma unroll
            for (int o = 1; o < 32; o <<= 1) {
                int t = __shfl_up_sync(0xffffffffu, w, o);
                if (lane >= o) w += t;
            }
            sWarp[lane] = w;
        }
        __syncthreads();
        int carry = sCarry;
        int woff  = wid ? sWarp[wid - 1] : 0;
        int excl  = carry + woff + v - c;
        if (i < N) { g_rowptr[i] = excl; g_cursor[i] = excl; }
        int total = sWarp[31];
        __syncthreads();
        if (tid == 0) sCarry = carry + total;
        __syncthreads();
    }
    if (tid == 0) g_rowptr[N] = sCarry;
}

__global__ void k_scatter(const int* __restrict__ src,
                          const int* __restrict__ dst, int E) {
    int e = blockIdx.x * blockDim.x + threadIdx.x;
    if (e < E) {
        int d = dst[e];
        int p = atomicAdd(&g_cursor[d], 1);
        g_csr_src[p] = src[e];
        g_csr_eid[p] = e;
    }
}

// ---------------- gather: agg_x[n] = sum_{e:dst=n} feat[src[e]] -------------
// warp per node, lane l accumulates components {2l, 2l+1}. Layer1 also sums
// edge_attr into g_agge (lanes 0..15).
template <bool L1>
__global__ void k_gather(const float* __restrict__ xfeat,
                         const float* __restrict__ ea, int N) {
    int warp = (blockIdx.x * blockDim.x + threadIdx.x) >> 5;
    int lane = threadIdx.x & 31;
    if (warp >= N) return;
    int beg = g_rowptr[warp], end = g_rowptr[warp + 1];
    const float2* f2 = (const float2*)(L1 ? xfeat : (const float*)g_h);
    float2 ax = make_float2(0.f, 0.f);
    float  ae = 0.f;
    for (int k = beg; k < end; k++) {
        int s = g_csr_src[k];
        float2 v = __ldg(&f2[s * 32 + lane]);
        ax.x += v.x; ax.y += v.y;
        if (L1) {
            int e = g_csr_eid[k];
            if (lane < EDGE_F) ae += __ldg(&ea[e * EDGE_F + lane]);
        }
    }
    ((float2*)g_aggx)[warp * 32 + lane] = ax;
    if (L1 && lane < EDGE_F) g_agge[warp * EDGE_F + lane] = ae;
}

// ---------------- node update: out = V[N,144] @ Wcat[144,OUT] + bias (+BN+ReLU)
// V = [feat(64) | agg(64) | agg_e(16)] staged in smem; W read from global
// (tiny, L1-resident). block: 64 nodes, blockDim (OUT/4, 16), 4x4 reg tiles.
#define VSTRIDE 148  // 144 + 4 pad

template <int OUT, bool BN, bool L1>
__global__ void k_node(const float* __restrict__ xfeat,
                       const float* __restrict__ Ws,   // [64, OUT]
                       const float* __restrict__ Wm,   // [80, OUT]
                       const float* __restrict__ bs,
                       const float* __restrict__ bm,
                       const float* __restrict__ gamma,
                       const float* __restrict__ beta,
                       const float* __restrict__ mean,
                       const float* __restrict__ var,
                       float* __restrict__ outp, int N) {
    __shared__ float sV[64 * VSTRIDE];
    __shared__ float sDeg[64];
    __shared__ float sBs[OUT], sBm[OUT], sScale[OUT], sShift[OUT];

    const float* feat = L1 ? xfeat : (const float*)g_h;
    float* out = L1 ? (float*)g_h : outp;

    int tid = threadIdx.y * blockDim.x + threadIdx.x;
    int nth = blockDim.x * blockDim.y;
    int nb = blockIdx.x * 64;
    int nn = N - nb; if (nn > 64) nn = 64;

    // stage V (feat | agg | agg_e)
    for (int i = tid; i < nn * 16; i += nth) {
        int n = i >> 4, c = i & 15;
        ((float4*)(sV + n * VSTRIDE))[c] = ((const float4*)feat)[(nb + n) * 16 + c];
    }
    for (int i = tid; i < nn * 16; i += nth) {
        int n = i >> 4, c = i & 15;
        ((float4*)(sV + n * VSTRIDE + 64))[c] = ((const float4*)g_aggx)[(nb + n) * 16 + c];
    }
    for (int i = tid; i < nn * 4; i += nth) {
        int n = i >> 2, c = i & 3;
        ((float4*)(sV + n * VSTRIDE + 128))[c] = ((const float4*)g_agge)[(nb + n) * 4 + c];
    }
    if (tid < nn)
        sDeg[tid] = (float)(g_rowptr[nb + tid + 1] - g_rowptr[nb + tid]);
    if (tid < OUT) {
        sBs[tid] = bs[tid];
        sBm[tid] = bm[tid];
        if constexpr (BN) {
            float s = gamma[tid] * rsqrtf(var[tid] + 1e-5f);
            sScale[tid] = s;
            sShift[tid] = beta[tid] - mean[tid] * s;
        }
    }
    __syncthreads();

    int tx = threadIdx.x, ty = threadIdx.y;
    float acc[4][4] = {};
    const float* vb = sV + (ty * 4) * VSTRIDE;

    const float4* WsCol = ((const float4*)Ws) + tx;   // stride OUT/4 float4s
    const float4* WmCol = ((const float4*)Wm) + tx;

    #pragma unroll 4
    for (int i = 0; i < 64; i++) {
        float4 w = __ldg(WsCol + i * (OUT / 4));
        float v0 = vb[i];
        float v1 = vb[VSTRIDE + i];
        float v2 = vb[2 * VSTRIDE + i];
        float v3 = vb[3 * VSTRIDE + i];
        acc[0][0] += v0 * w.x; acc[0][1] += v0 * w.y; acc[0][2] += v0 * w.z; acc[0][3] += v0 * w.w;
        acc[1][0] += v1 * w.x; acc[1][1] += v1 * w.y; acc[1][2] += v1 * w.z; acc[1][3] += v1 * w.w;
        acc[2][0] += v2 * w.x; acc[2][1] += v2 * w.y; acc[2][2] += v2 * w.z; acc[2][3] += v2 * w.w;
        acc[3][0] += v3 * w.x; acc[3][1] += v3 * w.y; acc[3][2] += v3 * w.z; acc[3][3] += v3 * w.w;
    }
    #pragma unroll 4
    for (int i = 0; i < 80; i++) {
        float4 w = __ldg(WmCol + i * (OUT / 4));
        float v0 = vb[64 + i];
        float v1 = vb[VSTRIDE + 64 + i];
        float v2 = vb[2 * VSTRIDE + 64 + i];
        float v3 = vb[3 * VSTRIDE + 64 + i];
        acc[0][0] += v0 * w.x; acc[0][1] += v0 * w.y; acc[0][2] += v0 * w.z; acc[0][3] += v0 * w.w;
        acc[1][0] += v1 * w.x; acc[1][1] += v1 * w.y; acc[1][2] += v1 * w.z; acc[1][3] += v1 * w.w;
        acc[2][0] += v2 * w.x; acc[2][1] += v2 * w.y; acc[2][2] += v2 * w.z; acc[2][3] += v2 * w.w;
        acc[3][0] += v3 * w.x; acc[3][1] += v3 * w.y; acc[3][2] += v3 * w.z; acc[3][3] += v3 * w.w;
    }

    #pragma unroll
    for (int r = 0; r < 4; r++) {
        int n = ty * 4 + r;
        if (n < nn) {
            float deg = sDeg[n];
            float4 o;
            float* op = (float*)&o;
            #pragma unroll
            for (int c = 0; c < 4; c++) {
                int j = tx * 4 + c;
                float a = acc[r][c] + sBs[j] + deg * sBm[j];
                if constexpr (BN) {
                    a = a * sScale[j] + sShift[j];
                    a = fmaxf(a, 0.f);
                }
                op[c] = a;
            }
            *(float4*)(out + (nb + n) * OUT + tx * 4) = o;
        }
    }
}

// ---------------- host ------------------------------------------------------
extern "C" void kernel_launch(void* const* d_in, const int* in_sizes, int n_in,
                              void* d_out, int out_size) {
    const float* x    = (const float*)d_in[0];
    const int*   ei   = (const int*)d_in[1];      // int32! (JAX x64 disabled)
    const float* ea   = (const float*)d_in[2];
    const float* W1m  = (const float*)d_in[3];
    const float* b1m  = (const float*)d_in[4];
    const float* W1s  = (const float*)d_in[5];
    const float* b1s  = (const float*)d_in[6];
    const float* gma  = (const float*)d_in[7];
    const float* bta  = (const float*)d_in[8];
    const float* mu   = (const float*)d_in[9];
    const float* var  = (const float*)d_in[10];
    const float* W2m  = (const float*)d_in[11];
    const float* b2m  = (const float*)d_in[12];
    const float* W2s  = (const float*)d_in[13];
    const float* b2s  = (const float*)d_in[14];
    float*       outp = (float*)d_out;

    int N = in_sizes[0] / NODE_F;
    int E = in_sizes[1] / 2;
    const int* src = ei;
    const int* dst = ei + E;

    // CSR build (dst-sorted)
    k_zero<<<(N + 255) / 256, 256>>>(N);
    k_hist<<<(E + 255) / 256, 256>>>(dst, E);
    k_scan<<<1, 1024>>>(N);
    k_scatter<<<(E + 255) / 256, 256>>>(src, dst, E);

    // Layer 1
    k_gather<true ><<<(N * 32 + 255) / 256, 256>>>(x, ea, N);
    k_node<64, true,  true ><<<(N + 63) / 64, dim3(16, 16)>>>(
        x, W1s, W1m, b1s, b1m, gma, bta, mu, var, outp, N);

    // Layer 2
    k_gather<false><<<(N * 32 + 255) / 256, 256>>>(x, ea, N);
    k_node<32, false, false><<<(N + 63) / 64, dim3(8, 16)>>>(
        x, W2s, W2m, b2s, b2m, nullptr, nullptr, nullptr, nullptr, outp, N);
}

// round 3
// speedup vs baseline: 1.0281x; 1.0281x over previous
#include <cuda_runtime.h>

// Problem constants (from reference)
#define NMAX 50000
#define EMAX 800000
#define NODE_F 64
#define EDGE_F 16
#define HID 64
#define OUTF 32

// ---------------- scratch (device globals; no allocation allowed) ----------
__device__ int   g_cnt[NMAX];
__device__ int   g_rowptr[NMAX + 1];
__device__ int   g_cursor[NMAX];
__device__ int   g_csr_src[EMAX];
__device__ int   g_csr_eid[EMAX];
__device__ float g_agge[NMAX * EDGE_F];   // segment_sum(edge_attr) — reused by both layers
__device__ float g_aggx[NMAX * 64];       // A@x (layer1), then A@h (layer2)
__device__ float g_h[NMAX * HID];         // post BN+ReLU hidden

// ---------------- CSR build ------------------------------------------------
__global__ void k_zero(int N) {
    int i = blockIdx.x * blockDim.x + threadIdx.x;
    if (i < N) g_cnt[i] = 0;
}

__global__ void k_hist(const int* __restrict__ dst, int E) {
    int e = blockIdx.x * blockDim.x + threadIdx.x;
    if (e < E) atomicAdd(&g_cnt[dst[e]], 1);
}

// single-block scan over N elements (exclusive prefix -> rowptr, cursor)
__global__ void k_scan(int N) {
    __shared__ int sWarp[32];
    __shared__ int sCarry;
    int tid = threadIdx.x;
    int lane = tid & 31, wid = tid >> 5;
    if (tid == 0) sCarry = 0;
    __syncthreads();
    for (int base = 0; base < N; base += 1024) {
        int i = base + tid;
        int c = (i < N) ? g_cnt[i] : 0;
        int v = c;
        #pragma unroll
        for (int o = 1; o < 32; o <<= 1) {
            int t = __shfl_up_sync(0xffffffffu, v, o);
            if (lane >= o) v += t;
        }
        if (lane == 31) sWarp[wid] = v;
        __syncthreads();
        if (wid == 0) {
            int w = sWarp[lane];
            #pragma unroll
            for (int o = 1; o < 32; o <<= 1) {
                int t = __shfl_up_sync(0xffffffffu, w, o);
                if (lane >= o) w += t;
            }
            sWarp[lane] = w;
        }
        __syncthreads();
        int carry = sCarry;
        int woff  = wid ? sWarp[wid - 1] : 0;
        int excl  = carry + woff + v - c;
        if (i < N) { g_rowptr[i] = excl; g_cursor[i] = excl; }
        int total = sWarp[31];
        __syncthreads();
        if (tid == 0) sCarry = carry + total;
        __syncthreads();
    }
    if (tid == 0) g_rowptr[N] = sCarry;
}

__global__ void k_scatter(const int* __restrict__ src,
                          const int* __restrict__ dst, int E) {
    int e = blockIdx.x * blockDim.x + threadIdx.x;
    if (e < E) {
        int d = dst[e];
        int p = atomicAdd(&g_cursor[d], 1);
        g_csr_src[p] = src[e];
        g_csr_eid[p] = e;
    }
}

// ---------------- gather: agg_x[n] = sum_{e:dst=n} feat[src[e]] -------------
// warp per node, lane l accumulates components {2l, 2l+1}. Layer1 also sums
// edge_attr into g_agge (lanes 0..15).
template <bool L1>
__global__ void k_gather(const float* __restrict__ xfeat,
                         const float* __restrict__ ea, int N) {
    int warp = (blockIdx.x * blockDim.x + threadIdx.x) >> 5;
    int lane = threadIdx.x & 31;
    if (warp >= N) return;
    int beg = g_rowptr[warp], end = g_rowptr[warp + 1];
    const float2* f2 = (const float2*)(L1 ? xfeat : (const float*)g_h);
    float2 ax = make_float2(0.f, 0.f);
    float  ae = 0.f;
    for (int k = beg; k < end; k++) {
        int s = g_csr_src[k];
        float2 v = __ldg(&f2[s * 32 + lane]);
        ax.x += v.x; ax.y += v.y;
        if (L1) {
            int e = g_csr_eid[k];
            if (lane < EDGE_F) ae += __ldg(&ea[e * EDGE_F + lane]);
        }
    }
    ((float2*)g_aggx)[warp * 32 + lane] = ax;
    if (L1 && lane < EDGE_F) g_agge[warp * EDGE_F + lane] = ae;
}

// ---------------- node update: out = V[N,144] @ Wcat[144,OUT] + bias (+BN+ReLU)
// V = [feat(64) | agg(64) | agg_e(16)] staged in smem; W read from global
// (tiny, L1-resident). block: 64 nodes, blockDim (OUT/4, 16), 4x4 reg tiles.
#define VSTRIDE 148  // 144 + 4 pad

template <int OUT, bool BN, bool L1>
__global__ void k_node(const float* __restrict__ xfeat,
                       const float* __restrict__ Ws,   // [64, OUT]
                       const float* __restrict__ Wm,   // [80, OUT]
                       const float* __restrict__ bs,
                       const float* __restrict__ bm,
                       const float* __restrict__ gamma,
                       const float* __restrict__ beta,
                       const float* __restrict__ mean,
                       const float* __restrict__ var,
                       float* __restrict__ outp, int N) {
    __shared__ float sV[64 * VSTRIDE];
    __shared__ float sDeg[64];
    __shared__ float sBs[OUT], sBm[OUT], sScale[OUT], sShift[OUT];

    const float* feat = L1 ? xfeat : (const float*)g_h;
    float* out = L1 ? (float*)g_h : outp;

    int tid = threadIdx.y * blockDim.x + threadIdx.x;
    int nth = blockDim.x * blockDim.y;
    int nb = blockIdx.x * 64;
    int nn = N - nb; if (nn > 64) nn = 64;

    // stage V (feat | agg | agg_e)
    for (int i = tid; i < nn * 16; i += nth) {
        int n = i >> 4, c = i & 15;
        ((float4*)(sV + n * VSTRIDE))[c] = ((const float4*)feat)[(nb + n) * 16 + c];
    }
    for (int i = tid; i < nn * 16; i += nth) {
        int n = i >> 4, c = i & 15;
        ((float4*)(sV + n * VSTRIDE + 64))[c] = ((const float4*)g_aggx)[(nb + n) * 16 + c];
    }
    for (int i = tid; i < nn * 4; i += nth) {
        int n = i >> 2, c = i & 3;
        ((float4*)(sV + n * VSTRIDE + 128))[c] = ((const float4*)g_agge)[(nb + n) * 4 + c];
    }
    if (tid < nn)
        sDeg[tid] = (float)(g_rowptr[nb + tid + 1] - g_rowptr[nb + tid]);
    if (tid < OUT) {
        sBs[tid] = bs[tid];
        sBm[tid] = bm[tid];
        if constexpr (BN) {
            float s = gamma[tid] * rsqrtf(var[tid] + 1e-5f);
            sScale[tid] = s;
            sShift[tid] = beta[tid] - mean[tid] * s;
        }
    }
    __syncthreads();

    int tx = threadIdx.x, ty = threadIdx.y;
    float acc[4][4] = {};
    const float* vb = sV + (ty * 4) * VSTRIDE;

    const float4* WsCol = ((const float4*)Ws) + tx;   // stride OUT/4 float4s
    const float4* WmCol = ((const float4*)Wm) + tx;

    #pragma unroll 4
    for (int i = 0; i < 64; i++) {
        float4 w = __ldg(WsCol + i * (OUT / 4));
        float v0 = vb[i];
        float v1 = vb[VSTRIDE + i];
        float v2 = vb[2 * VSTRIDE + i];
        float v3 = vb[3 * VSTRIDE + i];
        acc[0][0] += v0 * w.x; acc[0][1] += v0 * w.y; acc[0][2] += v0 * w.z; acc[0][3] += v0 * w.w;
        acc[1][0] += v1 * w.x; acc[1][1] += v1 * w.y; acc[1][2] += v1 * w.z; acc[1][3] += v1 * w.w;
        acc[2][0] += v2 * w.x; acc[2][1] += v2 * w.y; acc[2][2] += v2 * w.z; acc[2][3] += v2 * w.w;
        acc[3][0] += v3 * w.x; acc[3][1] += v3 * w.y; acc[3][2] += v3 * w.z; acc[3][3] += v3 * w.w;
    }
    #pragma unroll 4
    for (int i = 0; i < 80; i++) {
        float4 w = __ldg(WmCol + i * (OUT / 4));
        float v0 = vb[64 + i];
        float v1 = vb[VSTRIDE + 64 + i];
        float v2 = vb[2 * VSTRIDE + 64 + i];
        float v3 = vb[3 * VSTRIDE + 64 + i];
        acc[0][0] += v0 * w.x; acc[0][1] += v0 * w.y; acc[0][2] += v0 * w.z; acc[0][3] += v0 * w.w;
        acc[1][0] += v1 * w.x; acc[1][1] += v1 * w.y; acc[1][2] += v1 * w.z; acc[1][3] += v1 * w.w;
        acc[2][0] += v2 * w.x; acc[2][1] += v2 * w.y; acc[2][2] += v2 * w.z; acc[2][3] += v2 * w.w;
        acc[3][0] += v3 * w.x; acc[3][1] += v3 * w.y; acc[3][2] += v3 * w.z; acc[3][3] += v3 * w.w;
    }

    #pragma unroll
    for (int r = 0; r < 4; r++) {
        int n = ty * 4 + r;
        if (n < nn) {
            float deg = sDeg[n];
            float4 o;
            float* op = (float*)&o;
            #pragma unroll
            for (int c = 0; c < 4; c++) {
                int j = tx * 4 + c;
                float a = acc[r][c] + sBs[j] + deg * sBm[j];
                if constexpr (BN) {
                    a = a * sScale[j] + sShift[j];
                    a = fmaxf(a, 0.f);
                }
                op[c] = a;
            }
            *(float4*)(out + (nb + n) * OUT + tx * 4) = o;
        }
    }
}

// ---------------- host ------------------------------------------------------
extern "C" void kernel_launch(void* const* d_in, const int* in_sizes, int n_in,
                              void* d_out, int out_size) {
    const float* x    = (const float*)d_in[0];
    const int*   ei   = (const int*)d_in[1];      // int32! (JAX x64 disabled)
    const float* ea   = (const float*)d_in[2];
    const float* W1m  = (const float*)d_in[3];
    const float* b1m  = (const float*)d_in[4];
    const float* W1s  = (const float*)d_in[5];
    const float* b1s  = (const float*)d_in[6];
    const float* gma  = (const float*)d_in[7];
    const float* bta  = (const float*)d_in[8];
    const float* mu   = (const float*)d_in[9];
    const float* var  = (const float*)d_in[10];
    const float* W2m  = (const float*)d_in[11];
    const float* b2m  = (const float*)d_in[12];
    const float* W2s  = (const float*)d_in[13];
    const float* b2s  = (const float*)d_in[14];
    float*       outp = (float*)d_out;

    int N = in_sizes[0] / NODE_F;
    int E = in_sizes[1] / 2;
    const int* src = ei;
    const int* dst = ei + E;

    // CSR build (dst-sorted)
    k_zero<<<(N + 255) / 256, 256>>>(N);
    k_hist<<<(E + 255) / 256, 256>>>(dst, E);
    k_scan<<<1, 1024>>>(N);
    k_scatter<<<(E + 255) / 256, 256>>>(src, dst, E);

    // Layer 1
    k_gather<true ><<<(N * 32 + 255) / 256, 256>>>(x, ea, N);
    k_node<64, true,  true ><<<(N + 63) / 64, dim3(16, 16)>>>(
        x, W1s, W1m, b1s, b1m, gma, bta, mu, var, outp, N);

    // Layer 2
    k_gather<false><<<(N * 32 + 255) / 256, 256>>>(x, ea, N);
    k_node<32, false, false><<<(N + 63) / 64, dim3(8, 16)>>>(
        x, W2s, W2m, b2s, b2m, nullptr, nullptr, nullptr, nullptr, outp, N);
}

// round 4
// speedup vs baseline: 1.1382x; 1.1071x over previous
#include <cuda_runtime.h>

// Problem constants (from reference)
#define NMAX 50000
#define EMAX 800000
#define NODE_F 64
#define EDGE_F 16
#define HID 64
#define OUTF 32

// ---------------- scratch (device globals; no allocation allowed) ----------
__device__ int   g_cnt[NMAX];
__device__ int   g_rowptr[NMAX + 1];
__device__ int   g_cursor[NMAX];
__device__ int2  g_csr[EMAX];             // {src, eid} packed (one 8B store/edge)
__device__ int   g_blocksum[64];
__device__ int   g_blockoff[64];
__device__ float g_agge[NMAX * EDGE_F];   // segment_sum(edge_attr) — reused by both layers
__device__ float g_aggx[NMAX * 64];       // A@x (layer1), then A@h (layer2)
__device__ float g_h[NMAX * HID];         // post BN+ReLU hidden

// ---------------- CSR build ------------------------------------------------
__global__ void k_zero(int N) {
    int i = blockIdx.x * blockDim.x + threadIdx.x;
    if (i < N) g_cnt[i] = 0;
}

__global__ void k_hist(const int* __restrict__ dst, int E) {
    int e = blockIdx.x * blockDim.x + threadIdx.x;
    if (e < E) atomicAdd(&g_cnt[dst[e]], 1);
}

// ---- multi-block scan: A) per-1024-block sums  B) scan 49 sums  C) apply ---
__global__ void k_scanA(int N) {
    int i = blockIdx.x * 1024 + threadIdx.x;
    int lane = threadIdx.x & 31, wid = threadIdx.x >> 5;
    int v = (i < N) ? g_cnt[i] : 0;
    #pragma unroll
    for (int o = 16; o > 0; o >>= 1) v += __shfl_down_sync(0xffffffffu, v, o);
    __shared__ int sW[32];
    if (lane == 0) sW[wid] = v;
    __syncthreads();
    if (wid == 0) {
        int t = sW[lane];
        #pragma unroll
        for (int o = 16; o > 0; o >>= 1) t += __shfl_down_sync(0xffffffffu, t, o);
        if (lane == 0) g_blocksum[blockIdx.x] = t;
    }
}

__global__ void k_scanB(int nblk, int N) {
    // single block, 64 threads: exclusive scan of g_blocksum -> g_blockoff
    int tid = threadIdx.x;            // 0..63
    int lane = tid & 31, wid = tid >> 5;
    int c = (tid < nblk) ? g_blocksum[tid] : 0;
    int v = c;
    #pragma unroll
    for (int o = 1; o < 32; o <<= 1) {
        int t = __shfl_up_sync(0xffffffffu, v, o);
        if (lane >= o) v += t;
    }
    __shared__ int sTot[2];
    if (lane == 31) sTot[wid] = v;
    __syncthreads();
    int add = (wid == 1) ? sTot[0] : 0;
    int incl = v + add;
    g_blockoff[tid] = incl - c;
    if (tid == 63) g_rowptr[N] = incl;
}

__global__ void k_scanC(int N) {
    int b = blockIdx.x;
    int i = b * 1024 + threadIdx.x;
    int lane = threadIdx.x & 31, wid = threadIdx.x >> 5;
    int c = (i < N) ? g_cnt[i] : 0;
    int v = c;
    #pragma unroll
    for (int o = 1; o < 32; o <<= 1) {
        int t = __shfl_up_sync(0xffffffffu, v, o);
        if (lane >= o) v += t;
    }
    __shared__ int sW[32];
    if (lane == 31) sW[wid] = v;
    __syncthreads();
    if (wid == 0) {
        int w = sW[lane];
        #pragma unroll
        for (int o = 1; o < 32; o <<= 1) {
            int t = __shfl_up_sync(0xffffffffu, w, o);
            if (lane >= o) w += t;
        }
        sW[lane] = w;
    }
    __syncthreads();
    if (i < N) {
        int excl = g_blockoff[b] + (wid ? sW[wid - 1] : 0) + v - c;
        g_rowptr[i] = excl;
        g_cursor[i] = excl;
    }
}

__global__ void k_scatter(const int* __restrict__ src,
                          const int* __restrict__ dst, int E) {
    int e = blockIdx.x * blockDim.x + threadIdx.x;
    if (e < E) {
        int d = dst[e];
        int p = atomicAdd(&g_cursor[d], 1);
        g_csr[p] = make_int2(src[e], e);
    }
}

// ---------------- gather: agg_x[n] = sum_{e:dst=n} feat[src[e]] -------------
// warp per node, lane l holds feature components {2l, 2l+1}. 4x unrolled with
// independent accumulators to raise MLP. Layer1 also sums edge_attr (lanes<16).
template <bool L1>
__global__ void k_gather(const float* __restrict__ xfeat,
                         const float* __restrict__ ea, int N) {
    int warp = (blockIdx.x * blockDim.x + threadIdx.x) >> 5;
    int lane = threadIdx.x & 31;
    if (warp >= N) return;
    int beg = g_rowptr[warp], end = g_rowptr[warp + 1];
    const float2* f2 = (const float2*)(L1 ? xfeat : (const float*)g_h);

    float2 a0 = {0.f, 0.f}, a1 = {0.f, 0.f}, a2 = {0.f, 0.f}, a3 = {0.f, 0.f};
    float  e0s = 0.f, e1s = 0.f;

    int k = beg;
    for (; k + 4 <= end; k += 4) {
        int2 c0 = __ldg(&g_csr[k]);
        int2 c1 = __ldg(&g_csr[k + 1]);
        int2 c2 = __ldg(&g_csr[k + 2]);
        int2 c3 = __ldg(&g_csr[k + 3]);
        float2 v0 = __ldg(&f2[c0.x * 32 + lane]);
        float2 v1 = __ldg(&f2[c1.x * 32 + lane]);
        float2 v2 = __ldg(&f2[c2.x * 32 + lane]);
        float2 v3 = __ldg(&f2[c3.x * 32 + lane]);
        a0.x += v0.x; a0.y += v0.y;
        a1.x += v1.x; a1.y += v1.y;
        a2.x += v2.x; a2.y += v2.y;
        a3.x += v3.x; a3.y += v3.y;
        if (L1 && lane < EDGE_F) {
            float w0 = __ldg(&ea[c0.y * EDGE_F + lane]);
            float w1 = __ldg(&ea[c1.y * EDGE_F + lane]);
            float w2 = __ldg(&ea[c2.y * EDGE_F + lane]);
            float w3 = __ldg(&ea[c3.y * EDGE_F + lane]);
            e0s += w0 + w2;
            e1s += w1 + w3;
        }
    }
    for (; k < end; k++) {
        int2 c0 = __ldg(&g_csr[k]);
        float2 v0 = __ldg(&f2[c0.x * 32 + lane]);
        a0.x += v0.x; a0.y += v0.y;
        if (L1 && lane < EDGE_F) e0s += __ldg(&ea[c0.y * EDGE_F + lane]);
    }
    a0.x += a1.x + a2.x + a3.x;
    a0.y += a1.y + a2.y + a3.y;
    ((float2*)g_aggx)[warp * 32 + lane] = a0;
    if (L1 && lane < EDGE_F) g_agge[warp * EDGE_F + lane] = e0s + e1s;
}

// ---------------- node update: out = V[N,144] @ Wcat[144,OUT] + bias (+BN+ReLU)
// V = [feat(64) | agg(64) | agg_e(16)] staged in smem; W read from global
// (tiny, L1-resident). block: 64 nodes, blockDim (OUT/4, 16), 4x4 reg tiles.
#define VSTRIDE 148  // 144 + 4 pad

template <int OUT, bool BN, bool L1>
__global__ void k_node(const float* __restrict__ xfeat,
                       const float* __restrict__ Ws,   // [64, OUT]
                       const float* __restrict__ Wm,   // [80, OUT]
                       const float* __restrict__ bs,
                       const float* __restrict__ bm,
                       const float* __restrict__ gamma,
                       const float* __restrict__ beta,
                       const float* __restrict__ mean,
                       const float* __restrict__ var,
                       float* __restrict__ outp, int N) {
    __shared__ float sV[64 * VSTRIDE];
    __shared__ float sDeg[64];
    __shared__ float sBs[OUT], sBm[OUT], sScale[OUT], sShift[OUT];

    const float* feat = L1 ? xfeat : (const float*)g_h;
    float* out = L1 ? (float*)g_h : outp;

    int tid = threadIdx.y * blockDim.x + threadIdx.x;
    int nth = blockDim.x * blockDim.y;
    int nb = blockIdx.x * 64;
    int nn = N - nb; if (nn > 64) nn = 64;

    // stage V (feat | agg | agg_e)
    for (int i = tid; i < nn * 16; i += nth) {
        int n = i >> 4, c = i & 15;
        ((float4*)(sV + n * VSTRIDE))[c] = ((const float4*)feat)[(nb + n) * 16 + c];
    }
    for (int i = tid; i < nn * 16; i += nth) {
        int n = i >> 4, c = i & 15;
        ((float4*)(sV + n * VSTRIDE + 64))[c] = ((const float4*)g_aggx)[(nb + n) * 16 + c];
    }
    for (int i = tid; i < nn * 4; i += nth) {
        int n = i >> 2, c = i & 3;
        ((float4*)(sV + n * VSTRIDE + 128))[c] = ((const float4*)g_agge)[(nb + n) * 4 + c];
    }
    if (tid < nn)
        sDeg[tid] = (float)(g_rowptr[nb + tid + 1] - g_rowptr[nb + tid]);
    if (tid < OUT) {
        sBs[tid] = bs[tid];
        sBm[tid] = bm[tid];
        if constexpr (BN) {
            float s = gamma[tid] * rsqrtf(var[tid] + 1e-5f);
            sScale[tid] = s;
            sShift[tid] = beta[tid] - mean[tid] * s;
        }
    }
    __syncthreads();

    int tx = threadIdx.x, ty = threadIdx.y;
    float acc[4][4] = {};
    const float* vb = sV + (ty * 4) * VSTRIDE;

    const float4* WsCol = ((const float4*)Ws) + tx;   // stride OUT/4 float4s
    const float4* WmCol = ((const float4*)Wm) + tx;

    #pragma unroll 4
    for (int i = 0; i < 64; i++) {
        float4 w = __ldg(WsCol + i * (OUT / 4));
        float v0 = vb[i];
        float v1 = vb[VSTRIDE + i];
        float v2 = vb[2 * VSTRIDE + i];
        float v3 = vb[3 * VSTRIDE + i];
        acc[0][0] += v0 * w.x; acc[0][1] += v0 * w.y; acc[0][2] += v0 * w.z; acc[0][3] += v0 * w.w;
        acc[1][0] += v1 * w.x; acc[1][1] += v1 * w.y; acc[1][2] += v1 * w.z; acc[1][3] += v1 * w.w;
        acc[2][0] += v2 * w.x; acc[2][1] += v2 * w.y; acc[2][2] += v2 * w.z; acc[2][3] += v2 * w.w;
        acc[3][0] += v3 * w.x; acc[3][1] += v3 * w.y; acc[3][2] += v3 * w.z; acc[3][3] += v3 * w.w;
    }
    #pragma unroll 4
    for (int i = 0; i < 80; i++) {
        float4 w = __ldg(WmCol + i * (OUT / 4));
        float v0 = vb[64 + i];
        float v1 = vb[VSTRIDE + 64 + i];
        float v2 = vb[2 * VSTRIDE + 64 + i];
        float v3 = vb[3 * VSTRIDE + 64 + i];
        acc[0][0] += v0 * w.x; acc[0][1] += v0 * w.y; acc[0][2] += v0 * w.z; acc[0][3] += v0 * w.w;
        acc[1][0] += v1 * w.x; acc[1][1] += v1 * w.y; acc[1][2] += v1 * w.z; acc[1][3] += v1 * w.w;
        acc[2][0] += v2 * w.x; acc[2][1] += v2 * w.y; acc[2][2] += v2 * w.z; acc[2][3] += v2 * w.w;
        acc[3][0] += v3 * w.x; acc[3][1] += v3 * w.y; acc[3][2] += v3 * w.z; acc[3][3] += v3 * w.w;
    }

    #pragma unroll
    for (int r = 0; r < 4; r++) {
        int n = ty * 4 + r;
        if (n < nn) {
            float deg = sDeg[n];
            float4 o;
            float* op = (float*)&o;
            #pragma unroll
            for (int c = 0; c < 4; c++) {
                int j = tx * 4 + c;
                float a = acc[r][c] + sBs[j] + deg * sBm[j];
                if constexpr (BN) {
                    a = a * sScale[j] + sShift[j];
                    a = fmaxf(a, 0.f);
                }
                op[c] = a;
            }
            *(float4*)(out + (nb + n) * OUT + tx * 4) = o;
        }
    }
}

// ---------------- host ------------------------------------------------------
extern "C" void kernel_launch(void* const* d_in, const int* in_sizes, int n_in,
                              void* d_out, int out_size) {
    const float* x    = (const float*)d_in[0];
    const int*   ei   = (const int*)d_in[1];      // int32 (JAX x64 disabled)
    const float* ea   = (const float*)d_in[2];
    const float* W1m  = (const float*)d_in[3];
    const float* b1m  = (const float*)d_in[4];
    const float* W1s  = (const float*)d_in[5];
    const float* b1s  = (const float*)d_in[6];
    const float* gma  = (const float*)d_in[7];
    const float* bta  = (const float*)d_in[8];
    const float* mu   = (const float*)d_in[9];
    const float* var  = (const float*)d_in[10];
    const float* W2m  = (const float*)d_in[11];
    const float* b2m  = (const float*)d_in[12];
    const float* W2s  = (const float*)d_in[13];
    const float* b2s  = (const float*)d_in[14];
    float*       outp = (float*)d_out;

    int N = in_sizes[0] / NODE_F;
    int E = in_sizes[1] / 2;
    const int* src = ei;
    const int* dst = ei + E;
    int nblk = (N + 1023) / 1024;

    // CSR build (dst-sorted)
    k_zero<<<(N + 255) / 256, 256>>>(N);
    k_hist<<<(E + 255) / 256, 256>>>(dst, E);
    k_scanA<<<nblk, 1024>>>(N);
    k_scanB<<<1, 64>>>(nblk, N);
    k_scanC<<<nblk, 1024>>>(N);
    k_scatter<<<(E + 255) / 256, 256>>>(src, dst, E);

    // Layer 1
    k_gather<true ><<<(N * 32 + 255) / 256, 256>>>(x, ea, N);
    k_node<64, true,  true ><<<(N + 63) / 64, dim3(16, 16)>>>(
        x, W1s, W1m, b1s, b1m, gma, bta, mu, var, outp, N);

    // Layer 2
    k_gather<false><<<(N * 32 + 255) / 256, 256>>>(x, ea, N);
    k_node<32, false, false><<<(N + 63) / 64, dim3(8, 16)>>>(
        x, W2s, W2m, b2s, b2m, nullptr, nullptr, nullptr, nullptr, outp, N);
}

// round 5
// speedup vs baseline: 1.1793x; 1.0361x over previous
#include <cuda_runtime.h>

// Problem constants (from reference)
#define NMAX 50000
#define EMAX 800000
#define NODE_F 64
#define EDGE_F 16
#define HID 64
#define OUTF 32

// ---------------- f32x2 helpers (sm_103a FFMA2 path) ------------------------
#define DUP_F32X2(d, f) \
    asm("mov.b64 %0, {%1, %1};" : "=l"(d) : "f"(f))
#define PACK_F32X2(d, lo, hi) \
    asm("mov.b64 %0, {%1, %2};" : "=l"(d) : "f"(lo), "f"(hi))
#define UNPACK_F32X2(lo, hi, v) \
    asm("mov.b64 {%0, %1}, %2;" : "=f"(lo), "=f"(hi) : "l"(v))
#define FFMA2(d, a, b, c) \
    asm("fma.rn.f32x2 %0, %1, %2, %3;" : "=l"(d) : "l"(a), "l"(b), "l"(c))

// ---------------- scratch (device globals; no allocation allowed) ----------
__device__ int   g_cnt[NMAX];
__device__ int   g_rowptr[NMAX + 1];
__device__ int   g_cursor[NMAX];
__device__ int2  g_csr[EMAX];             // {src, eid} packed
__device__ int   g_blocksum[64];
__device__ float g_agge[NMAX * EDGE_F];   // segment_sum(edge_attr), reused by L2
__device__ float g_h[NMAX * HID];         // post BN+ReLU hidden

// ---------------- CSR build ------------------------------------------------
__global__ void k_zero(int N) {
    int i = blockIdx.x * blockDim.x + threadIdx.x;
    if (i < N) g_cnt[i] = 0;
}

__global__ void k_hist(const int* __restrict__ dst, int E) {
    int e = blockIdx.x * blockDim.x + threadIdx.x;
    if (e < E) atomicAdd(&g_cnt[dst[e]], 1);
}

// per-1024-block sums
__global__ void k_scanA(int N) {
    int i = blockIdx.x * 1024 + threadIdx.x;
    int lane = threadIdx.x & 31, wid = threadIdx.x >> 5;
    int v = (i < N) ? g_cnt[i] : 0;
    #pragma unroll
    for (int o = 16; o > 0; o >>= 1) v += __shfl_down_sync(0xffffffffu, v, o);
    __shared__ int sW[32];
    if (lane == 0) sW[wid] = v;
    __syncthreads();
    if (wid == 0) {
        int t = sW[lane];
        #pragma unroll
        for (int o = 16; o > 0; o >>= 1) t += __shfl_down_sync(0xffffffffu, t, o);
        if (lane == 0) g_blocksum[blockIdx.x] = t;
    }
}

// per-element scan; each block computes its own offset from g_blocksum
__global__ void k_scanC(int N, int E) {
    int b = blockIdx.x;
    int i = b * 1024 + threadIdx.x;
    int lane = threadIdx.x & 31, wid = threadIdx.x >> 5;
    __shared__ int sW[32];
    __shared__ int sOff;
    if (wid == 0) {
        int s = 0;
        if (lane < b) s += g_blocksum[lane];
        if (lane + 32 < b) s += g_blocksum[lane + 32];
        #pragma unroll
        for (int o = 16; o > 0; o >>= 1) s += __shfl_down_sync(0xffffffffu, s, o);
        if (lane == 0) sOff = s;
    }
    int c = (i < N) ? g_cnt[i] : 0;
    int v = c;
    #pragma unroll
    for (int o = 1; o < 32; o <<= 1) {
        int t = __shfl_up_sync(0xffffffffu, v, o);
        if (lane >= o) v += t;
    }
    if (lane == 31) sW[wid] = v;
    __syncthreads();
    if (wid == 0) {
        int w = sW[lane];
        #pragma unroll
        for (int o = 1; o < 32; o <<= 1) {
            int t = __shfl_up_sync(0xffffffffu, w, o);
            if (lane >= o) w += t;
        }
        sW[lane] = w;
    }
    __syncthreads();
    if (i < N) {
        int excl = sOff + (wid ? sW[wid - 1] : 0) + v - c;
        g_rowptr[i] = excl;
        g_cursor[i] = excl;
    }
    if (b == 0 && threadIdx.x == 0) g_rowptr[N] = E;
}

__global__ void k_scatter(const int* __restrict__ src,
                          const int* __restrict__ dst, int E) {
    int e = blockIdx.x * blockDim.x + threadIdx.x;
    if (e < E) {
        int d = dst[e];
        int p = atomicAdd(&g_cursor[d], 1);
        g_csr[p] = make_int2(src[e], e);
    }
}

// ---------------- fused layer: gather + node GEMM ---------------------------
// Block: 64 nodes, 256 threads.
//  A) stage feat (L2: + agge) into transposed smem sVT[k][node]
//  B) warp-per-node gather of A@feat into sVT rows 64..127 (L1: agge 128..143)
//  C) register-tiled GEMM with FFMA2 (f32x2): out = V[64,144] @ Wcat[144,OUT]
#define SSTR 66   // transposed stride (even for LDS.64 alignment; 66%32=2)

template <int OUT, bool BN, bool L1>
__global__ __launch_bounds__(256) void k_layer(
    const float* __restrict__ xfeat, const float* __restrict__ ea,
    const float* __restrict__ Ws,   // [64, OUT]
    const float* __restrict__ Wm,   // [80, OUT]
    const float* __restrict__ bs, const float* __restrict__ bm,
    const float* __restrict__ gamma, const float* __restrict__ beta,
    const float* __restrict__ mean, const float* __restrict__ var,
    float* __restrict__ outp, int N)
{
    __shared__ __align__(16) float sVT[144 * SSTR];
    __shared__ float sDeg[64];

    const float* feat = L1 ? xfeat : (const float*)g_h;
    float* out = L1 ? (float*)g_h : outp;

    int tid = threadIdx.x;
    int nb = blockIdx.x * 64;
    int nn = N - nb; if (nn > 64) nn = 64;

    // --- A: stage feat rows 0..63 (transposed) ---
    for (int idx = tid; idx < nn * 16; idx += 256) {
        int n = idx >> 4, c = idx & 15;
        float4 f = __ldg(&((const float4*)feat)[(nb + n) * 16 + c]);
        sVT[(4 * c + 0) * SSTR + n] = f.x;
        sVT[(4 * c + 1) * SSTR + n] = f.y;
        sVT[(4 * c + 2) * SSTR + n] = f.z;
        sVT[(4 * c + 3) * SSTR + n] = f.w;
    }
    if (!L1) {  // stage agge rows 128..143 from global (computed in L1)
        for (int idx = tid; idx < nn * 4; idx += 256) {
            int n = idx >> 2, c = idx & 3;
            float4 f = __ldg(&((const float4*)g_agge)[(nb + n) * 4 + c]);
            sVT[(128 + 4 * c + 0) * SSTR + n] = f.x;
            sVT[(128 + 4 * c + 1) * SSTR + n] = f.y;
            sVT[(128 + 4 * c + 2) * SSTR + n] = f.z;
            sVT[(128 + 4 * c + 3) * SSTR + n] = f.w;
        }
    }

    // --- B: gather (warp per node, 8 warps round-robin) ---
    {
        int w = tid >> 5, lane = tid & 31;
        const float2* f2 = (const float2*)feat;
        for (int nl = w; nl < nn; nl += 8) {
            int node = nb + nl;
            int beg = g_rowptr[node], end = g_rowptr[node + 1];
            float2 a0 = {0.f, 0.f}, a1 = {0.f, 0.f}, a2 = {0.f, 0.f}, a3 = {0.f, 0.f};
            float e0s = 0.f, e1s = 0.f;
            int k = beg;
            for (; k + 4 <= end; k += 4) {
                int2 c0 = __ldg(&g_csr[k]);
                int2 c1 = __ldg(&g_csr[k + 1]);
                int2 c2 = __ldg(&g_csr[k + 2]);
                int2 c3 = __ldg(&g_csr[k + 3]);
                float2 v0 = __ldg(&f2[c0.x * 32 + lane]);
                float2 v1 = __ldg(&f2[c1.x * 32 + lane]);
                float2 v2 = __ldg(&f2[c2.x * 32 + lane]);
                float2 v3 = __ldg(&f2[c3.x * 32 + lane]);
                a0.x += v0.x; a0.y += v0.y;
                a1.x += v1.x; a1.y += v1.y;
                a2.x += v2.x; a2.y += v2.y;
                a3.x += v3.x; a3.y += v3.y;
                if (L1 && lane < EDGE_F) {
                    float w0 = __ldg(&ea[c0.y * EDGE_F + lane]);
                    float w1 = __ldg(&ea[c1.y * EDGE_F + lane]);
                    float w2 = __ldg(&ea[c2.y * EDGE_F + lane]);
                    float w3 = __ldg(&ea[c3.y * EDGE_F + lane]);
                    e0s += w0 + w2;
                    e1s += w1 + w3;
                }
            }
            for (; k < end; k++) {
                int2 c0 = __ldg(&g_csr[k]);
                float2 v0 = __ldg(&f2[c0.x * 32 + lane]);
                a0.x += v0.x; a0.y += v0.y;
                if (L1 && lane < EDGE_F) e0s += __ldg(&ea[c0.y * EDGE_F + lane]);
            }
            a0.x += a1.x + a2.x + a3.x;
            a0.y += a1.y + a2.y + a3.y;
            sVT[(64 + 2 * lane + 0) * SSTR + nl] = a0.x;
            sVT[(64 + 2 * lane + 1) * SSTR + nl] = a0.y;
            if (L1 && lane < EDGE_F) {
                float ae = e0s + e1s;
                sVT[(128 + lane) * SSTR + nl] = ae;
                g_agge[node * EDGE_F + lane] = ae;   // reused by layer 2
            }
            if (lane == 0) sDeg[nl] = (float)(end - beg);
        }
    }
    __syncthreads();

    // --- C: GEMM with FFMA2 ---
    constexpr int TXN  = OUT / 4;       // float4 cols: 16 (L1) / 8 (L2)
    constexpr int ROWS = TXN / 4;       // nodes per thread: 4 (L1) / 2 (L2)
    constexpr int NP   = ROWS / 2;      // node-pairs: 2 / 1
    int tx = tid % TXN, ty = tid / TXN;
    int r0 = ty * ROWS;

    unsigned long long acc2[NP][4];
    #pragma unroll
    for (int p = 0; p < NP; p++)
        #pragma unroll
        for (int c = 0; c < 4; c++) acc2[p][c] = 0ull;

    const float4* WsP = (const float4*)Ws + tx;
    const float4* WmP = (const float4*)Wm + tx;

    #pragma unroll 4
    for (int i = 0; i < 64; i++) {
        float4 w4 = __ldg(WsP + i * TXN);
        unsigned long long wd0, wd1, wd2, wd3;
        DUP_F32X2(wd0, w4.x); DUP_F32X2(wd1, w4.y);
        DUP_F32X2(wd2, w4.z); DUP_F32X2(wd3, w4.w);
        #pragma unroll
        for (int p = 0; p < NP; p++) {
            unsigned long long v2 =
                *(const unsigned long long*)&sVT[i * SSTR + r0 + 2 * p];
            FFMA2(acc2[p][0], v2, wd0, acc2[p][0]);
            FFMA2(acc2[p][1], v2, wd1, acc2[p][1]);
            FFMA2(acc2[p][2], v2, wd2, acc2[p][2]);
            FFMA2(acc2[p][3], v2, wd3, acc2[p][3]);
        }
    }
    #pragma unroll 4
    for (int i = 0; i < 80; i++) {
        float4 w4 = __ldg(WmP + i * TXN);
        unsigned long long wd0, wd1, wd2, wd3;
        DUP_F32X2(wd0, w4.x); DUP_F32X2(wd1, w4.y);
        DUP_F32X2(wd2, w4.z); DUP_F32X2(wd3, w4.w);
        #pragma unroll
        for (int p = 0; p < NP; p++) {
            unsigned long long v2 =
                *(const unsigned long long*)&sVT[(64 + i) * SSTR + r0 + 2 * p];
            FFMA2(acc2[p][0], v2, wd0, acc2[p][0]);
            FFMA2(acc2[p][1], v2, wd1, acc2[p][1]);
            FFMA2(acc2[p][2], v2, wd2, acc2[p][2]);
            FFMA2(acc2[p][3], v2, wd3, acc2[p][3]);
        }
    }

    // --- epilogue ---
    float4 bsv = __ldg((const float4*)bs + tx);
    float4 bmv = __ldg((const float4*)bm + tx);
    float4 scv = {0, 0, 0, 0}, shv = {0, 0, 0, 0};
    if constexpr (BN) {
        float4 g = __ldg((const float4*)gamma + tx);
        float4 vv = __ldg((const float4*)var + tx);
        float4 mv = __ldg((const float4*)mean + tx);
        float4 bv = __ldg((const float4*)beta + tx);
        scv.x = g.x * rsqrtf(vv.x + 1e-5f); shv.x = bv.x - mv.x * scv.x;
        scv.y = g.y * rsqrtf(vv.y + 1e-5f); shv.y = bv.y - mv.y * scv.y;
        scv.z = g.z * rsqrtf(vv.z + 1e-5f); shv.z = bv.z - mv.z * scv.z;
        scv.w = g.w * rsqrtf(vv.w + 1e-5f); shv.w = bv.w - mv.w * scv.w;
    }
    #pragma unroll
    for (int p = 0; p < NP; p++) {
        float lo[4], hi[4];
        #pragma unroll
        for (int c = 0; c < 4; c++) UNPACK_F32X2(lo[c], hi[c], acc2[p][c]);
        #pragma unroll
        for (int h = 0; h < 2; h++) {
            int r = r0 + 2 * p + h;
            if (r < nn) {
                float deg = sDeg[r];
                float4 o;
                o.x = (h ? hi[0] : lo[0]) + bsv.x + deg * bmv.x;
                o.y = (h ? hi[1] : lo[1]) + bsv.y + deg * bmv.y;
                o.z = (h ? hi[2] : lo[2]) + bsv.z + deg * bmv.z;
                o.w = (h ? hi[3] : lo[3]) + bsv.w + deg * bmv.w;
                if constexpr (BN) {
                    o.x = fmaxf(o.x * scv.x + shv.x, 0.f);
                    o.y = fmaxf(o.y * scv.y + shv.y, 0.f);
                    o.z = fmaxf(o.z * scv.z + shv.z, 0.f);
                    o.w = fmaxf(o.w * scv.w + shv.w, 0.f);
                }
                *(float4*)(out + (nb + r) * OUT + tx * 4) = o;
            }
        }
    }
}

// ---------------- host ------------------------------------------------------
extern "C" void kernel_launch(void* const* d_in, const int* in_sizes, int n_in,
                              void* d_out, int out_size) {
    const float* x    = (const float*)d_in[0];
    const int*   ei   = (const int*)d_in[1];      // int32 (JAX x64 disabled)
    const float* ea   = (const float*)d_in[2];
    const float* W1m  = (const float*)d_in[3];
    const float* b1m  = (const float*)d_in[4];
    const float* W1s  = (const float*)d_in[5];
    const float* b1s  = (const float*)d_in[6];
    const float* gma  = (const float*)d_in[7];
    const float* bta  = (const float*)d_in[8];
    const float* mu   = (const float*)d_in[9];
    const float* var  = (const float*)d_in[10];
    const float* W2m  = (const float*)d_in[11];
    const float* b2m  = (const float*)d_in[12];
    const float* W2s  = (const float*)d_in[13];
    const float* b2s  = (const float*)d_in[14];
    float*       outp = (float*)d_out;

    int N = in_sizes[0] / NODE_F;
    int E = in_sizes[1] / 2;
    const int* src = ei;
    const int* dst = ei + E;
    int nblk = (N + 1023) / 1024;

    // CSR build (dst-sorted)
    k_zero<<<(N + 255) / 256, 256>>>(N);
    k_hist<<<(E + 255) / 256, 256>>>(dst, E);
    k_scanA<<<nblk, 1024>>>(N);
    k_scanC<<<nblk, 1024>>>(N, E);
    k_scatter<<<(E + 255) / 256, 256>>>(src, dst, E);

    // fused layers
    k_layer<64, true,  true ><<<(N + 63) / 64, 256>>>(
        x, ea, W1s, W1m, b1s, b1m, gma, bta, mu, var, outp, N);
    k_layer<32, false, false><<<(N + 63) / 64, 256>>>(
        x, ea, W2s, W2m, b2s, b2m, nullptr, nullptr, nullptr, nullptr, outp, N);
}

// round 6
// speedup vs baseline: 1.3268x; 1.1250x over previous
#include <cuda_runtime.h>

#define NMAX 50000
#define EMAX 800000

// ---------------- f32x2 helpers (sm_103a FFMA2) -----------------------------
#define DUP_F32X2(d, f) \
    asm("mov.b64 %0, {%1, %1};" : "=l"(d) : "f"(f))
#define UNPACK_F32X2(lo, hi, v) \
    asm("mov.b64 {%0, %1}, %2;" : "=f"(lo), "=f"(hi) : "l"(v))
#define FFMA2(d, a, b, c) \
    asm("fma.rn.f32x2 %0, %1, %2, %3;" : "=l"(d) : "l"(a), "l"(b), "l"(c))

__device__ __forceinline__ float4 f4add(float4 a, float4 b) {
    return make_float4(a.x + b.x, a.y + b.y, a.z + b.z, a.w + b.w);
}
__device__ __forceinline__ float4 f4fma(float s, float4 w, float4 a) {
    return make_float4(fmaf(s, w.x, a.x), fmaf(s, w.y, a.y),
                       fmaf(s, w.z, a.z), fmaf(s, w.w, a.w));
}

// ---------------- scratch (device globals) ----------------------------------
__device__ int    g_cnt[NMAX];
__device__ int    g_rowptr[NMAX + 1];
__device__ int    g_cursor[NMAX];
__device__ int2   g_csr[EMAX];
__device__ int    g_blocksum[64];
__device__ float4 g_p1[NMAX * 16];    // x @ W1m_x  [N,64]
__device__ float4 g_s1[NMAX * 16];    // x @ W1s    [N,64]
__device__ float4 g_p2[NMAX * 8];     // h @ W2m_x  [N,32]
__device__ float4 g_s2[NMAX * 8];     // h @ W2s    [N,32]
__device__ float4 g_aggp[NMAX * 16];  // gathered projections (L1 64w / L2 32w)
__device__ float4 g_agge[NMAX * 4];   // segment_sum(edge_attr) [N,16]

// ---------------- CSR build ------------------------------------------------
__global__ void k_zero(int N) {
    int i = blockIdx.x * blockDim.x + threadIdx.x;
    if (i < N) g_cnt[i] = 0;
}

__global__ void k_hist(const int* __restrict__ dst, int E) {
    int e = blockIdx.x * blockDim.x + threadIdx.x;
    if (e < E) atomicAdd(&g_cnt[dst[e]], 1);
}

__global__ void k_scanA(int N) {
    int i = blockIdx.x * 1024 + threadIdx.x;
    int lane = threadIdx.x & 31, wid = threadIdx.x >> 5;
    int v = (i < N) ? g_cnt[i] : 0;
    #pragma unroll
    for (int o = 16; o > 0; o >>= 1) v += __shfl_down_sync(0xffffffffu, v, o);
    __shared__ int sW[32];
    if (lane == 0) sW[wid] = v;
    __syncthreads();
    if (wid == 0) {
        int t = sW[lane];
        #pragma unroll
        for (int o = 16; o > 0; o >>= 1) t += __shfl_down_sync(0xffffffffu, t, o);
        if (lane == 0) g_blocksum[blockIdx.x] = t;
    }
}

__global__ void k_scanC(int N, int E) {
    int b = blockIdx.x;
    int i = b * 1024 + threadIdx.x;
    int lane = threadIdx.x & 31, wid = threadIdx.x >> 5;
    __shared__ int sW[32];
    __shared__ int sOff;
    if (wid == 0) {
        int s = 0;
        if (lane < b) s += g_blocksum[lane];
        if (lane + 32 < b) s += g_blocksum[lane + 32];
        #pragma unroll
        for (int o = 16; o > 0; o >>= 1) s += __shfl_down_sync(0xffffffffu, s, o);
        if (lane == 0) sOff = s;
    }
    int c = (i < N) ? g_cnt[i] : 0;
    int v = c;
    #pragma unroll
    for (int o = 1; o < 32; o <<= 1) {
        int t = __shfl_up_sync(0xffffffffu, v, o);
        if (lane >= o) v += t;
    }
    if (lane == 31) sW[wid] = v;
    __syncthreads();
    if (wid == 0) {
        int w = sW[lane];
        #pragma unroll
        for (int o = 1; o < 32; o <<= 1) {
            int t = __shfl_up_sync(0xffffffffu, w, o);
            if (lane >= o) w += t;
        }
        sW[lane] = w;
    }
    __syncthreads();
    if (i < N) {
        int excl = sOff + (wid ? sW[wid - 1] : 0) + v - c;
        g_rowptr[i] = excl;
        g_cursor[i] = excl;
    }
    if (b == 0 && threadIdx.x == 0) g_rowptr[N] = E;
}

__global__ void k_scatter(const int* __restrict__ src,
                          const int* __restrict__ dst, int E) {
    int e = blockIdx.x * blockDim.x + threadIdx.x;
    if (e < E) {
        int d = dst[e];
        int p = atomicAdd(&g_cursor[d], 1);
        g_csr[p] = make_int2(src[e], e);
    }
}

// ---------------- proj1: P1 = x@W1m[:64], S1 = x@W1s ------------------------
// 64 nodes/block, 256 threads; K=64, OUT=128 (two 64-wide outputs).
__global__ __launch_bounds__(256) void k_proj1(
    const float4* __restrict__ x4,
    const float4* __restrict__ W1m4,   // [80,64] -> f4 row stride 16
    const float4* __restrict__ W1s4,   // [64,64] -> f4 row stride 16
    int N)
{
    __shared__ __align__(16) float sXT[64 * 66];
    int tid = threadIdx.x;
    int nb = blockIdx.x * 64;
    int nn = N - nb; if (nn > 64) nn = 64;

    for (int idx = tid; idx < nn * 16; idx += 256) {
        int n = idx >> 4, c = idx & 15;
        float4 f = __ldg(&x4[(nb + n) * 16 + c]);
        sXT[(4 * c + 0) * 66 + n] = f.x;
        sXT[(4 * c + 1) * 66 + n] = f.y;
        sXT[(4 * c + 2) * 66 + n] = f.z;
        sXT[(4 * c + 3) * 66 + n] = f.w;
    }
    __syncthreads();

    int tx = tid & 31, ty = tid >> 5;    // 32 f4-cols, 8 node-groups
    int r0 = ty * 8;
    unsigned long long acc2[4][4];
    #pragma unroll
    for (int p = 0; p < 4; p++)
        #pragma unroll
        for (int c = 0; c < 4; c++) acc2[p][c] = 0ull;

    const float4* Wp = (tx < 16) ? (W1m4 + tx) : (W1s4 + (tx - 16));
    #pragma unroll 4
    for (int i = 0; i < 64; i++) {
        float4 w4 = __ldg(Wp + i * 16);
        unsigned long long wd0, wd1, wd2, wd3;
        DUP_F32X2(wd0, w4.x); DUP_F32X2(wd1, w4.y);
        DUP_F32X2(wd2, w4.z); DUP_F32X2(wd3, w4.w);
        #pragma unroll
        for (int p = 0; p < 4; p++) {
            unsigned long long v2 =
                *(const unsigned long long*)&sXT[i * 66 + r0 + 2 * p];
            FFMA2(acc2[p][0], v2, wd0, acc2[p][0]);
            FFMA2(acc2[p][1], v2, wd1, acc2[p][1]);
            FFMA2(acc2[p][2], v2, wd2, acc2[p][2]);
            FFMA2(acc2[p][3], v2, wd3, acc2[p][3]);
        }
    }

    float4* dst = (tx < 16) ? g_p1 : g_s1;
    int txo = (tx < 16) ? tx : tx - 16;
    #pragma unroll
    for (int p = 0; p < 4; p++) {
        float lo[4], hi[4];
        #pragma unroll
        for (int c = 0; c < 4; c++) UNPACK_F32X2(lo[c], hi[c], acc2[p][c]);
        int r = r0 + 2 * p;
        if (r < nn)
            dst[(nb + r) * 16 + txo] = make_float4(lo[0], lo[1], lo[2], lo[3]);
        if (r + 1 < nn)
            dst[(nb + r + 1) * 16 + txo] = make_float4(hi[0], hi[1], hi[2], hi[3]);
    }
}

// ---------------- gather: aggp[n] = sum_{e:dst=n} P[src[e]] -----------------
// quarter-warp per node (8 lanes, float4 components), 2-edge unroll.
template <bool L1>
__global__ __launch_bounds__(256) void k_gather(const float4* __restrict__ ea4, int N) {
    int warp = (blockIdx.x * 256 + threadIdx.x) >> 5;
    int lane = threadIdx.x & 31;
    int g = lane >> 3, j = lane & 7;
    int node = warp * 4 + g;
    if (node >= N) return;
    int beg = g_rowptr[node];
    int cnt = g_rowptr[node + 1] - beg;
    const int2* csr = g_csr + beg;

    if (L1) {
        const float4* f4 = g_p1;
        float4 a0 = {0,0,0,0}, b0 = a0, a1 = a0, b1 = a0, e0 = a0, e1 = a0;
        int k = 0;
        for (; k + 2 <= cnt; k += 2) {
            int2 c0 = csr[k], c1 = csr[k + 1];
            float4 v00 = __ldg(&f4[c0.x * 16 + 2 * j]);
            float4 v01 = __ldg(&f4[c0.x * 16 + 2 * j + 1]);
            float4 v10 = __ldg(&f4[c1.x * 16 + 2 * j]);
            float4 v11 = __ldg(&f4[c1.x * 16 + 2 * j + 1]);
            if (j < 4) {
                e0 = f4add(e0, __ldg(&ea4[c0.y * 4 + j]));
                e1 = f4add(e1, __ldg(&ea4[c1.y * 4 + j]));
            }
            a0 = f4add(a0, v00); b0 = f4add(b0, v01);
            a1 = f4add(a1, v10); b1 = f4add(b1, v11);
        }
        if (k < cnt) {
            int2 c0 = csr[k];
            a0 = f4add(a0, __ldg(&f4[c0.x * 16 + 2 * j]));
            b0 = f4add(b0, __ldg(&f4[c0.x * 16 + 2 * j + 1]));
            if (j < 4) e0 = f4add(e0, __ldg(&ea4[c0.y * 4 + j]));
        }
        g_aggp[node * 16 + 2 * j]     = f4add(a0, a1);
        g_aggp[node * 16 + 2 * j + 1] = f4add(b0, b1);
        if (j < 4) g_agge[node * 4 + j] = f4add(e0, e1);
    } else {
        const float4* f4 = g_p2;
        float4 a0 = {0,0,0,0}, a1 = a0, a2 = a0, a3 = a0;
        int k = 0;
        for (; k + 4 <= cnt; k += 4) {
            int2 c0 = csr[k], c1 = csr[k + 1], c2 = csr[k + 2], c3 = csr[k + 3];
            a0 = f4add(a0, __ldg(&f4[c0.x * 8 + j]));
            a1 = f4add(a1, __ldg(&f4[c1.x * 8 + j]));
            a2 = f4add(a2, __ldg(&f4[c2.x * 8 + j]));
            a3 = f4add(a3, __ldg(&f4[c3.x * 8 + j]));
        }
        for (; k < cnt; k++) {
            int2 c0 = csr[k];
            a0 = f4add(a0, __ldg(&f4[c0.x * 8 + j]));
        }
        g_aggp[node * 8 + j] = f4add(f4add(a0, a1), f4add(a2, a3));
    }
}

// ---------------- node1 + proj2 ---------------------------------------------
// h = ReLU(BN(S1 + b1s + aggp1 + agge@W1m_e + deg*b1m)); then
// P2 = h@W2m[:64], S2 = h@W2s  (h lives only in smem).
__global__ __launch_bounds__(256) void k_node1p2(
    const float* __restrict__ W1m,     // [80,64] scalar (edge rows 64..79)
    const float* __restrict__ b1s, const float* __restrict__ b1m,
    const float* __restrict__ gamma, const float* __restrict__ beta,
    const float* __restrict__ mean, const float* __restrict__ var,
    const float4* __restrict__ W2m4,   // [80,32] -> f4 row stride 8
    const float4* __restrict__ W2s4,   // [64,32] -> f4 row stride 8
    int N)
{
    __shared__ __align__(16) float sHT[64 * 66];
    int tid = threadIdx.x;
    int nb = blockIdx.x * 64;
    int nn = N - nb; if (nn > 64) nn = 64;

    // --- phase A: compute h for 64 nodes (thread = node x 16-col group) ---
    {
        int n = tid >> 2;
        int cg = (tid & 3) * 4;   // f4-col base (4 f4 = 16 scalar cols)
        if (n < nn) {
            int node = nb + n;
            float deg = (float)(g_rowptr[node + 1] - g_rowptr[node]);
            float4 eg4[4];
            #pragma unroll
            for (int q = 0; q < 4; q++) eg4[q] = g_agge[node * 4 + q];
            float eg[16] = {eg4[0].x, eg4[0].y, eg4[0].z, eg4[0].w,
                            eg4[1].x, eg4[1].y, eg4[1].z, eg4[1].w,
                            eg4[2].x, eg4[2].y, eg4[2].z, eg4[2].w,
                            eg4[3].x, eg4[3].y, eg4[3].z, eg4[3].w};
            float4 acc[4];
            #pragma unroll
            for (int q = 0; q < 4; q++) {
                float4 s  = g_s1[node * 16 + cg + q];
                float4 a  = g_aggp[node * 16 + cg + q];
                float4 bS = __ldg(&((const float4*)b1s)[cg + q]);
                float4 bM = __ldg(&((const float4*)b1m)[cg + q]);
                acc[q] = make_float4(s.x + a.x + bS.x + deg * bM.x,
                                     s.y + a.y + bS.y + deg * bM.y,
                                     s.z + a.z + bS.z + deg * bM.z,
                                     s.w + a.w + bS.w + deg * bM.w);
            }
            #pragma unroll
            for (int jj = 0; jj < 16; jj++) {
                float ev = eg[jj];
                const float4* wrow = (const float4*)(W1m + (64 + jj) * 64) + cg;
                #pragma unroll
                for (int q = 0; q < 4; q++)
                    acc[q] = f4fma(ev, __ldg(&wrow[q]), acc[q]);
            }
            #pragma unroll
            for (int q = 0; q < 4; q++) {
                float4 gm = __ldg(&((const float4*)gamma)[cg + q]);
                float4 vv = __ldg(&((const float4*)var)[cg + q]);
                float4 mn = __ldg(&((const float4*)mean)[cg + q]);
                float4 bt = __ldg(&((const float4*)beta)[cg + q]);
                float scx = gm.x * rsqrtf(vv.x + 1e-5f);
                float scy = gm.y * rsqrtf(vv.y + 1e-5f);
                float scz = gm.z * rsqrtf(vv.z + 1e-5f);
                float scw = gm.w * rsqrtf(vv.w + 1e-5f);
                float hx = fmaxf(acc[q].x * scx + (bt.x - mn.x * scx), 0.f);
                float hy = fmaxf(acc[q].y * scy + (bt.y - mn.y * scy), 0.f);
                float hz = fmaxf(acc[q].z * scz + (bt.z - mn.z * scz), 0.f);
                float hw = fmaxf(acc[q].w * scw + (bt.w - mn.w * scw), 0.f);
                int c0 = (cg + q) * 4;
                sHT[(c0 + 0) * 66 + n] = hx;
                sHT[(c0 + 1) * 66 + n] = hy;
                sHT[(c0 + 2) * 66 + n] = hz;
                sHT[(c0 + 3) * 66 + n] = hw;
            }
        }
    }
    __syncthreads();

    // --- phase B: GEMM h[64,64] @ [W2m_x | W2s][64,64] -> P2, S2 ---
    int tx = tid & 15, ty = tid >> 4;   // 16 f4-cols, 16 node-groups
    int r0 = ty * 4;
    unsigned long long acc2[2][4];
    #pragma unroll
    for (int p = 0; p < 2; p++)
        #pragma unroll
        for (int c = 0; c < 4; c++) acc2[p][c] = 0ull;

    const float4* Wp = (tx < 8) ? (W2m4 + tx) : (W2s4 + (tx - 8));
    #pragma unroll 4
    for (int i = 0; i < 64; i++) {
        float4 w4 = __ldg(Wp + i * 8);
        unsigned long long wd0, wd1, wd2, wd3;
        DUP_F32X2(wd0, w4.x); DUP_F32X2(wd1, w4.y);
        DUP_F32X2(wd2, w4.z); DUP_F32X2(wd3, w4.w);
        #pragma unroll
        for (int p = 0; p < 2; p++) {
            unsigned long long v2 =
                *(const unsigned long long*)&sHT[i * 66 + r0 + 2 * p];
            FFMA2(acc2[p][0], v2, wd0, acc2[p][0]);
            FFMA2(acc2[p][1], v2, wd1, acc2[p][1]);
            FFMA2(acc2[p][2], v2, wd2, acc2[p][2]);
            FFMA2(acc2[p][3], v2, wd3, acc2[p][3]);
        }
    }

    float4* dst = (tx < 8) ? g_p2 : g_s2;
    int txo = (tx < 8) ? tx : tx - 8;
    #pragma unroll
    for (int p = 0; p < 2; p++) {
        float lo[4], hi[4];
        #pragma unroll
        for (int c = 0; c < 4; c++) UNPACK_F32X2(lo[c], hi[c], acc2[p][c]);
        int r = r0 + 2 * p;
        if (r < nn)
            dst[(nb + r) * 8 + txo] = make_float4(lo[0], lo[1], lo[2], lo[3]);
        if (r + 1 < nn)
            dst[(nb + r + 1) * 8 + txo] = make_float4(hi[0], hi[1], hi[2], hi[3]);
    }
}

// ---------------- node2: out = S2 + b2s + aggp2 + deg*b2m + agge@W2m_e ------
__global__ __launch_bounds__(256) void k_node2(
    const float4* __restrict__ W2m4,   // [80,32] -> f4 row stride 8
    const float* __restrict__ b2s, const float* __restrict__ b2m,
    float4* __restrict__ out4, int N)
{
    int gid = blockIdx.x * 256 + threadIdx.x;
    int n = gid >> 2;
    int cq = gid & 3;     // 2 f4 cols: 2cq, 2cq+1
    if (n >= N) return;
    float deg = (float)(g_rowptr[n + 1] - g_rowptr[n]);
    float4 eg4[4];
    #pragma unroll
    for (int q = 0; q < 4; q++) eg4[q] = g_agge[n * 4 + q];
    float eg[16] = {eg4[0].x, eg4[0].y, eg4[0].z, eg4[0].w,
                    eg4[1].x, eg4[1].y, eg4[1].z, eg4[1].w,
                    eg4[2].x, eg4[2].y, eg4[2].z, eg4[2].w,
                    eg4[3].x, eg4[3].y, eg4[3].z, eg4[3].w};
    float4 s0 = g_s2[n * 8 + 2 * cq],   s1 = g_s2[n * 8 + 2 * cq + 1];
    float4 a0 = g_aggp[n * 8 + 2 * cq], a1 = g_aggp[n * 8 + 2 * cq + 1];
    float4 bS0 = __ldg(&((const float4*)b2s)[2 * cq]);
    float4 bS1 = __ldg(&((const float4*)b2s)[2 * cq + 1]);
    float4 bM0 = __ldg(&((const float4*)b2m)[2 * cq]);
    float4 bM1 = __ldg(&((const float4*)b2m)[2 * cq + 1]);
    float4 o0 = make_float4(s0.x + a0.x + bS0.x + deg * bM0.x,
                            s0.y + a0.y + bS0.y + deg * bM0.y,
                            s0.z + a0.z + bS0.z + deg * bM0.z,
                            s0.w + a0.w + bS0.w + deg * bM0.w);
    float4 o1 = make_float4(s1.x + a1.x + bS1.x + deg * bM1.x,
                            s1.y + a1.y + bS1.y + deg * bM1.y,
                            s1.z + a1.z + bS1.z + deg * bM1.z,
                            s1.w + a1.w + bS1.w + deg * bM1.w);
    #pragma unroll
    for (int jj = 0; jj < 16; jj++) {
        float ev = eg[jj];
        o0 = f4fma(ev, __ldg(&W2m4[(64 + jj) * 8 + 2 * cq]), o0);
        o1 = f4fma(ev, __ldg(&W2m4[(64 + jj) * 8 + 2 * cq + 1]), o1);
    }
    out4[n * 8 + 2 * cq]     = o0;
    out4[n * 8 + 2 * cq + 1] = o1;
}

// ---------------- host ------------------------------------------------------
extern "C" void kernel_launch(void* const* d_in, const int* in_sizes, int n_in,
                              void* d_out, int out_size) {
    const float* x    = (const float*)d_in[0];
    const int*   ei   = (const int*)d_in[1];      // int32 (JAX x64 disabled)
    const float* ea   = (const float*)d_in[2];
    const float* W1m  = (const float*)d_in[3];
    const float* b1m  = (const float*)d_in[4];
    const float* W1s  = (const float*)d_in[5];
    const float* b1s  = (const float*)d_in[6];
    const float* gma  = (const float*)d_in[7];
    const float* bta  = (const float*)d_in[8];
    const float* mu   = (const float*)d_in[9];
    const float* var  = (const float*)d_in[10];
    const float* W2m  = (const float*)d_in[11];
    const float* b2m  = (const float*)d_in[12];
    const float* W2s  = (const float*)d_in[13];
    const float* b2s  = (const float*)d_in[14];

    int N = in_sizes[0] / 64;
    int E = in_sizes[1] / 2;
    const int* src = ei;
    const int* dst = ei + E;
    int nblk = (N + 1023) / 1024;
    int nodeblk = (N + 63) / 64;
    int gatherblk = (N * 8 + 255) / 256;   // 4 nodes per warp

    // CSR build (dst-sorted)
    k_zero<<<(N + 255) / 256, 256>>>(N);
    k_hist<<<(E + 255) / 256, 256>>>(dst, E);
    k_scanA<<<nblk, 1024>>>(N);
    k_scanC<<<nblk, 1024>>>(N, E);
    k_scatter<<<(E + 255) / 256, 256>>>(src, dst, E);

    // layer 1
    k_proj1<<<nodeblk, 256>>>((const float4*)x, (const float4*)W1m,
                              (const float4*)W1s, N);
    k_gather<true><<<gatherblk, 256>>>((const float4*)ea, N);
    k_node1p2<<<nodeblk, 256>>>(W1m, b1s, b1m, gma, bta, mu, var,
                                (const float4*)W2m, (const float4*)W2s, N);
    // layer 2
    k_gather<false><<<gatherblk, 256>>>((const float4*)ea, N);
    k_node2<<<(N * 4 + 255) / 256, 256>>>((const float4*)W2m, b2s, b2m,
                                          (float4*)d_out, N);
}